// round 8
// baseline (speedup 1.0000x reference)
#include <cuda_runtime.h>

#define M_ROWS   2048
#define NDIM     128
#define NN       (NDIM * NDIM)       // 16384 complex entries of matH
#define NV4      (NN / 4)            // 4096 float4 per row per component
#define TASK_F4  256                 // float4 per task per component (2 iters x 128)
#define TPR      16                  // tasks per row
#define NTASKS   (M_ROWS * TPR)      // 32768 tasks of 8 KB each
#define THREADS  1024

// Device scratch (allocation-free rule: __device__ globals)
__device__ float2   g_part[NTASKS];  // one partial per task (256 KB)
__device__ unsigned g_ctr = 0;

// ---------------------------------------------------------------------------
// Single fused kernel:
//  phase A: every block builds matH in its 128 KB smem
//  phase B: static-stride 8 KB tasks (96% balance), boundary = shuffle chain
//           (~1% of task time) + ONE 8-byte store
//  phase C: last-arriving block sums the 256 KB partial array (L2-resident)
// ---------------------------------------------------------------------------
__global__ __launch_bounds__(THREADS, 1) void fused_kernel(
    const float* __restrict__ bre, const float* __restrict__ bim,
    const float* __restrict__ theta, const float* __restrict__ evl,
    float* __restrict__ out)
{
    extern __shared__ float sh[];             // 2 * NN floats = 128 KB
    float* hre = sh;
    float* him = sh + NN;

    __shared__ float e0r[NDIM], e0i[NDIM], e1r[NDIM], e1i[NDIM];
    __shared__ float wred[THREADS / 32];
    __shared__ float sc[6];
    __shared__ unsigned slast;

    const int tid  = threadIdx.x;
    const int lane = tid & 31;
    const int warp = tid >> 5;

    // ---------------- phase A: eigvectors + matH ----------------
    float th0 = 0.f, th1 = 0.f, th2 = 0.f, th3 = 0.f;
    if (tid < NDIM) {
        th0 = theta[tid];
        th1 = theta[NDIM + tid];
        th2 = theta[2 * NDIM + tid];
        th3 = theta[3 * NDIM + tid];
    }

    auto blockReduce = [&](float v, int slot) -> float {
        #pragma unroll
        for (int o = 16; o; o >>= 1) v += __shfl_xor_sync(0xffffffffu, v, o);
        if (lane == 0) wred[warp] = v;
        __syncthreads();
        if (tid == 0) {
            float s = 0.f;
            #pragma unroll
            for (int i = 0; i < THREADS / 32; i++) s += wred[i];
            sc[slot] = s;
        }
        __syncthreads();
        return sc[slot];
    };

    const float s0   = blockReduce(th0 * th0 + th1 * th1, 0);
    const float inv0 = rsqrtf(s0);
    const float a0 = th0 * inv0, b0 = th1 * inv0;           // evc0
    const float dr = blockReduce(a0 * th2 + b0 * th3, 1);   // Re vdot(evc0,c1)
    const float di = blockReduce(a0 * th3 - b0 * th2, 2);   // Im vdot(evc0,c1)
    const float c1r = th2 - (dr * a0 - di * b0);
    const float c1i = th3 - (dr * b0 + di * a0);
    const float s1   = blockReduce(c1r * c1r + c1i * c1i, 3);
    const float inv1 = rsqrtf(s1);

    if (tid < NDIM) {
        e0r[tid] = a0;         e0i[tid] = b0;
        e1r[tid] = c1r * inv1; e1i[tid] = c1i * inv1;
    }
    if (tid == 0) {
        const float l0 = log1pf(expf(evl[0]));
        const float l1 = log1pf(expf(evl[1]));
        const float nl = rsqrtf(l0 * l0 + l1 * l1);
        sc[4] = l0 * nl;                                     // lam0
        sc[5] = l1 * nl;                                     // lam1
    }
    __syncthreads();
    const float lam0 = sc[4], lam1 = sc[5];

    #pragma unroll
    for (int k = 0; k < NN / THREADS; k++) {
        const int c = tid + k * THREADS;                     // stride-1 writes
        const int i = c >> 7, j = c & (NDIM - 1);
        const float A0 = e0r[i], B0 = e0i[i], A1 = e1r[i], B1 = e1i[i];
        const float aj0 = e0r[j], bj0 = e0i[j], aj1 = e1r[j], bj1 = e1i[j];
        hre[c] = lam0 * (A0 * aj0 + B0 * bj0) - lam1 * (A1 * aj1 + B1 * bj1);
        him[c] = lam0 * (B0 * aj0 - A0 * bj0) - lam1 * (B1 * aj1 - A1 * bj1);
    }
    __syncthreads();

    // ---------------- phase B: 8KB-task streaming ----------------
    // v = (re - i*im) . (hre + i*him):
    //   vr += re*hre + im*him ;  vi += re*him - im*hre
    const float4* hre4 = (const float4*)hre;
    const float4* him4 = (const float4*)him;
    const int gw = blockIdx.x * (THREADS / 32) + warp;       // global warp id
    const int nw = gridDim.x * (THREADS / 32);               // total warps

    for (int t = gw; t < NTASKS; t += nw) {
        const int row = t >> 4;                              // 0..2047
        const int cb  = (t & (TPR - 1)) * TASK_F4;           // float4 offset in row
        const int hb  = cb + lane;
        const float4* br = (const float4*)bre + (size_t)row * NV4 + cb + lane;
        const float4* bi = (const float4*)bim + (size_t)row * NV4 + cb + lane;

        float vr = 0.f, vi = 0.f;
        #pragma unroll 1
        for (int it = 0; it < 2; it++) {                     // 2 x 128 float4
            const int c = it * 128;
            const float4 r0 = __ldcs(br + c);
            const float4 r1 = __ldcs(br + c + 32);
            const float4 r2 = __ldcs(br + c + 64);
            const float4 r3 = __ldcs(br + c + 96);
            const float4 m0 = __ldcs(bi + c);
            const float4 m1 = __ldcs(bi + c + 32);
            const float4 m2 = __ldcs(bi + c + 64);
            const float4 m3 = __ldcs(bi + c + 96);

            float4 h, g;
            h = hre4[hb + c];      g = him4[hb + c];
            vr += r0.x*h.x + m0.x*g.x;  vi += r0.x*g.x - m0.x*h.x;
            vr += r0.y*h.y + m0.y*g.y;  vi += r0.y*g.y - m0.y*h.y;
            vr += r0.z*h.z + m0.z*g.z;  vi += r0.z*g.z - m0.z*h.z;
            vr += r0.w*h.w + m0.w*g.w;  vi += r0.w*g.w - m0.w*h.w;
            h = hre4[hb + c + 32]; g = him4[hb + c + 32];
            vr += r1.x*h.x + m1.x*g.x;  vi += r1.x*g.x - m1.x*h.x;
            vr += r1.y*h.y + m1.y*g.y;  vi += r1.y*g.y - m1.y*h.y;
            vr += r1.z*h.z + m1.z*g.z;  vi += r1.z*g.z - m1.z*h.z;
            vr += r1.w*h.w + m1.w*g.w;  vi += r1.w*g.w - m1.w*h.w;
            h = hre4[hb + c + 64]; g = him4[hb + c + 64];
            vr += r2.x*h.x + m2.x*g.x;  vi += r2.x*g.x - m2.x*h.x;
            vr += r2.y*h.y + m2.y*g.y;  vi += r2.y*g.y - m2.y*h.y;
            vr += r2.z*h.z + m2.z*g.z;  vi += r2.z*g.z - m2.z*h.z;
            vr += r2.w*h.w + m2.w*g.w;  vi += r2.w*g.w - m2.w*h.w;
            h = hre4[hb + c + 96]; g = him4[hb + c + 96];
            vr += r3.x*h.x + m3.x*g.x;  vi += r3.x*g.x - m3.x*h.x;
            vr += r3.y*h.y + m3.y*g.y;  vi += r3.y*g.y - m3.y*h.y;
            vr += r3.z*h.z + m3.z*g.z;  vi += r3.z*g.z - m3.z*h.z;
            vr += r3.w*h.w + m3.w*g.w;  vi += r3.w*g.w - m3.w*h.w;
        }
        // boundary: full warp reduce (~130 cyc, ~1% of task time), one store
        #pragma unroll
        for (int o = 16; o; o >>= 1) {
            vr += __shfl_xor_sync(0xffffffffu, vr, o);
            vi += __shfl_xor_sync(0xffffffffu, vi, o);
        }
        if (lane == 0) g_part[t] = make_float2(vr, vi);
    }

    // ---------------- phase C: last block reduces 256 KB ----------------
    __syncthreads();
    if (tid == 0) {
        __threadfence();
        const unsigned old = atomicAdd(&g_ctr, 1u);
        slast = (old == gridDim.x - 1) ? 1u : 0u;
        if (slast) g_ctr = 0;                                // reset for replay
    }
    __syncthreads();

    if (slast) {
        __threadfence();
        float acc = 0.f;
        #pragma unroll 1
        for (int r = tid; r < M_ROWS; r += THREADS) {        // 2 rows per thread
            // 16 float2 partials per row = 32 floats = 8 float4, contiguous
            const float4* pp = (const float4*)(g_part + (size_t)r * TPR);
            const float4 q0 = __ldcg(pp);
            const float4 q1 = __ldcg(pp + 1);
            const float4 q2 = __ldcg(pp + 2);
            const float4 q3 = __ldcg(pp + 3);
            const float4 q4 = __ldcg(pp + 4);
            const float4 q5 = __ldcg(pp + 5);
            const float4 q6 = __ldcg(pp + 6);
            const float4 q7 = __ldcg(pp + 7);
            const float vr = ((q0.x + q0.z) + (q1.x + q1.z))
                           + ((q2.x + q2.z) + (q3.x + q3.z))
                           + ((q4.x + q4.z) + (q5.x + q5.z))
                           + ((q6.x + q6.z) + (q7.x + q7.z));
            const float vi = ((q0.y + q0.w) + (q1.y + q1.w))
                           + ((q2.y + q2.w) + (q3.y + q3.w))
                           + ((q4.y + q4.w) + (q5.y + q5.w))
                           + ((q6.y + q6.w) + (q7.y + q7.w));
            acc += vr * vr + vi * vi;
        }
        #pragma unroll
        for (int o = 16; o; o >>= 1) acc += __shfl_xor_sync(0xffffffffu, acc, o);
        if (lane == 0) wred[warp] = acc;
        __syncthreads();
        if (warp == 0) {
            float v = wred[lane];
            #pragma unroll
            for (int o = 16; o; o >>= 1) v += __shfl_xor_sync(0xffffffffu, v, o);
            if (lane == 0) out[0] = v;
        }
    }
}

// ---------------------------------------------------------------------------
extern "C" void kernel_launch(void* const* d_in, const int* in_sizes, int n_in,
                              void* d_out, int out_size) {
    const float* bre   = (const float*)d_in[0];
    const float* bim   = (const float*)d_in[1];
    const float* theta = (const float*)d_in[2];
    const float* evl   = (const float*)d_in[3];

    int sms = 148;
    cudaDeviceGetAttribute(&sms, cudaDevAttrMultiProcessorCount, 0);

    const int smem = 2 * NN * (int)sizeof(float);            // 128 KB
    cudaFuncSetAttribute(fused_kernel, cudaFuncAttributeMaxDynamicSharedMemorySize, smem);

    fused_kernel<<<sms, THREADS, smem>>>(bre, bim, theta, evl, (float*)d_out);
}

// round 11
// speedup vs baseline: 1.1559x; 1.1559x over previous
#include <cuda_runtime.h>

#define M_ROWS   2048
#define NDIM     128
#define NN       (NDIM * NDIM)       // 16384 complex entries of matH
#define NV4      (NN / 4)            // 4096 float4 per row per component
#define TASK_F4  256                 // float4 per task per component (2 iters x 128)
#define TPR      16                  // tasks per row
#define NTASKS   (M_ROWS * TPR)      // 32768 tasks of 8 KB each
#define THREADS  1024

// Device scratch (allocation-free rule: __device__ globals)
__device__ float2   g_part[NTASKS * 16];  // 16 half-lane partials per task (4 MB)
__device__ float    g_bsum[512];          // per-block sums (grid <= 512)
__device__ unsigned g_ctr1 = 0;
__device__ unsigned g_ctr2 = 0;

// ---------------------------------------------------------------------------
// Single fused persistent kernel (1 block/SM, all blocks co-resident):
//  phase A: every block builds matH in its 128 KB smem
//  phase B: static-stride 8 KB tasks, boundary = ONE shuffle + half-warp store
//           (the R6 engine: best measured streaming engine)
//  phase C: grid-wide counter barrier, then ALL blocks cooperatively reduce
//           the 4 MB partial array. Layout: row r owns float2 [r*256, r*256+256)
//           = 128 float4. Warp-per-row, 4 float4 per lane. Deterministic.
// ---------------------------------------------------------------------------
__global__ __launch_bounds__(THREADS, 1) void fused_kernel(
    const float* __restrict__ bre, const float* __restrict__ bim,
    const float* __restrict__ theta, const float* __restrict__ evl,
    float* __restrict__ out)
{
    extern __shared__ float sh[];             // 2 * NN floats = 128 KB
    float* hre = sh;
    float* him = sh + NN;

    __shared__ float e0r[NDIM], e0i[NDIM], e1r[NDIM], e1i[NDIM];
    __shared__ float wred[THREADS / 32];
    __shared__ float sc[6];
    __shared__ unsigned slast;

    const int tid  = threadIdx.x;
    const int lane = tid & 31;
    const int warp = tid >> 5;

    // ---------------- phase A: eigvectors + matH ----------------
    float th0 = 0.f, th1 = 0.f, th2 = 0.f, th3 = 0.f;
    if (tid < NDIM) {
        th0 = theta[tid];
        th1 = theta[NDIM + tid];
        th2 = theta[2 * NDIM + tid];
        th3 = theta[3 * NDIM + tid];
    }

    auto blockReduce = [&](float v, int slot) -> float {
        #pragma unroll
        for (int o = 16; o; o >>= 1) v += __shfl_xor_sync(0xffffffffu, v, o);
        if (lane == 0) wred[warp] = v;
        __syncthreads();
        if (tid == 0) {
            float s = 0.f;
            #pragma unroll
            for (int i = 0; i < THREADS / 32; i++) s += wred[i];
            sc[slot] = s;
        }
        __syncthreads();
        return sc[slot];
    };

    const float s0   = blockReduce(th0 * th0 + th1 * th1, 0);
    const float inv0 = rsqrtf(s0);
    const float a0 = th0 * inv0, b0 = th1 * inv0;           // evc0
    const float dr = blockReduce(a0 * th2 + b0 * th3, 1);   // Re vdot(evc0,c1)
    const float di = blockReduce(a0 * th3 - b0 * th2, 2);   // Im vdot(evc0,c1)
    const float c1r = th2 - (dr * a0 - di * b0);
    const float c1i = th3 - (dr * b0 + di * a0);
    const float s1   = blockReduce(c1r * c1r + c1i * c1i, 3);
    const float inv1 = rsqrtf(s1);

    if (tid < NDIM) {
        e0r[tid] = a0;         e0i[tid] = b0;
        e1r[tid] = c1r * inv1; e1i[tid] = c1i * inv1;
    }
    if (tid == 0) {
        const float l0 = log1pf(expf(evl[0]));
        const float l1 = log1pf(expf(evl[1]));
        const float nl = rsqrtf(l0 * l0 + l1 * l1);
        sc[4] = l0 * nl;                                     // lam0
        sc[5] = l1 * nl;                                     // lam1
    }
    __syncthreads();
    const float lam0 = sc[4], lam1 = sc[5];

    #pragma unroll
    for (int k = 0; k < NN / THREADS; k++) {
        const int c = tid + k * THREADS;                     // stride-1 writes
        const int i = c >> 7, j = c & (NDIM - 1);
        const float A0 = e0r[i], B0 = e0i[i], A1 = e1r[i], B1 = e1i[i];
        const float aj0 = e0r[j], bj0 = e0i[j], aj1 = e1r[j], bj1 = e1i[j];
        hre[c] = lam0 * (A0 * aj0 + B0 * bj0) - lam1 * (A1 * aj1 + B1 * bj1);
        him[c] = lam0 * (B0 * aj0 - A0 * bj0) - lam1 * (B1 * aj1 - A1 * bj1);
    }
    __syncthreads();

    // ---------------- phase B: 8KB-task streaming (R6 engine) ----------------
    // v = (re - i*im) . (hre + i*him):
    //   vr += re*hre + im*him ;  vi += re*him - im*hre
    const float4* hre4 = (const float4*)hre;
    const float4* him4 = (const float4*)him;
    const int gw = blockIdx.x * (THREADS / 32) + warp;       // global warp id
    const int nw = gridDim.x * (THREADS / 32);               // total warps

    for (int t = gw; t < NTASKS; t += nw) {
        const int row = t >> 4;                              // 0..2047
        const int cb  = (t & (TPR - 1)) * TASK_F4;           // float4 offset in row
        const int hb  = cb + lane;
        const float4* br = (const float4*)bre + (size_t)row * NV4 + cb + lane;
        const float4* bi = (const float4*)bim + (size_t)row * NV4 + cb + lane;

        float vr = 0.f, vi = 0.f;
        #pragma unroll 1
        for (int it = 0; it < 2; it++) {                     // 2 x 128 float4
            const int c = it * 128;
            const float4 r0 = __ldcs(br + c);
            const float4 r1 = __ldcs(br + c + 32);
            const float4 r2 = __ldcs(br + c + 64);
            const float4 r3 = __ldcs(br + c + 96);
            const float4 m0 = __ldcs(bi + c);
            const float4 m1 = __ldcs(bi + c + 32);
            const float4 m2 = __ldcs(bi + c + 64);
            const float4 m3 = __ldcs(bi + c + 96);

            float4 h, g;
            h = hre4[hb + c];      g = him4[hb + c];
            vr += r0.x*h.x + m0.x*g.x;  vi += r0.x*g.x - m0.x*h.x;
            vr += r0.y*h.y + m0.y*g.y;  vi += r0.y*g.y - m0.y*h.y;
            vr += r0.z*h.z + m0.z*g.z;  vi += r0.z*g.z - m0.z*h.z;
            vr += r0.w*h.w + m0.w*g.w;  vi += r0.w*g.w - m0.w*h.w;
            h = hre4[hb + c + 32]; g = him4[hb + c + 32];
            vr += r1.x*h.x + m1.x*g.x;  vi += r1.x*g.x - m1.x*h.x;
            vr += r1.y*h.y + m1.y*g.y;  vi += r1.y*g.y - m1.y*h.y;
            vr += r1.z*h.z + m1.z*g.z;  vi += r1.z*g.z - m1.z*h.z;
            vr += r1.w*h.w + m1.w*g.w;  vi += r1.w*g.w - m1.w*h.w;
            h = hre4[hb + c + 64]; g = him4[hb + c + 64];
            vr += r2.x*h.x + m2.x*g.x;  vi += r2.x*g.x - m2.x*h.x;
            vr += r2.y*h.y + m2.y*g.y;  vi += r2.y*g.y - m2.y*h.y;
            vr += r2.z*h.z + m2.z*g.z;  vi += r2.z*g.z - m2.z*h.z;
            vr += r2.w*h.w + m2.w*g.w;  vi += r2.w*g.w - m2.w*h.w;
            h = hre4[hb + c + 96]; g = him4[hb + c + 96];
            vr += r3.x*h.x + m3.x*g.x;  vi += r3.x*g.x - m3.x*h.x;
            vr += r3.y*h.y + m3.y*g.y;  vi += r3.y*g.y - m3.y*h.y;
            vr += r3.z*h.z + m3.z*g.z;  vi += r3.z*g.z - m3.z*h.z;
            vr += r3.w*h.w + m3.w*g.w;  vi += r3.w*g.w - m3.w*h.w;
        }
        // boundary: ONE shuffle, half-warp 8B stores (128B coalesced)
        vr += __shfl_xor_sync(0xffffffffu, vr, 16);
        vi += __shfl_xor_sync(0xffffffffu, vi, 16);
        if (lane < 16) g_part[(size_t)t * 16 + lane] = make_float2(vr, vi);
    }

    // ---------------- phase C: grid barrier + distributed reduce ----------------
    __syncthreads();
    if (tid == 0) {
        __threadfence();
        atomicAdd(&g_ctr1, 1u);
        while (*(volatile unsigned*)&g_ctr1 < gridDim.x) __nanosleep(64);
    }
    __syncthreads();
    __threadfence();                                         // acquire partials

    // warp-per-row: row r owns 256 float2 = 128 float4; 4 float4 per lane
    {
        const int rowW = blockIdx.x * (THREADS / 32) + warp;
        float sq = 0.f;
        if (rowW < M_ROWS) {
            const float4* pp = (const float4*)(g_part + (size_t)rowW * 256);
            const float4 qa = __ldcg(pp + lane);             // float4   0.. 31
            const float4 qb = __ldcg(pp + lane + 32);        // float4  32.. 63
            const float4 qc = __ldcg(pp + lane + 64);        // float4  64.. 95
            const float4 qd = __ldcg(pp + lane + 96);        // float4  96..127
            float vr = ((qa.x + qa.z) + (qb.x + qb.z))
                     + ((qc.x + qc.z) + (qd.x + qd.z));
            float vi = ((qa.y + qa.w) + (qb.y + qb.w))
                     + ((qc.y + qc.w) + (qd.y + qd.w));
            #pragma unroll
            for (int o = 16; o; o >>= 1) {
                vr += __shfl_xor_sync(0xffffffffu, vr, o);
                vi += __shfl_xor_sync(0xffffffffu, vi, o);
            }
            sq = vr * vr + vi * vi;                          // valid on all lanes
        }
        if (lane == 0) wred[warp] = sq;                      // 0 for idle warps
    }
    __syncthreads();
    if (tid == 0) {
        float s = 0.f;
        #pragma unroll
        for (int i = 0; i < THREADS / 32; i++) s += wred[i]; // fixed order
        g_bsum[blockIdx.x] = s;
        __threadfence();
        const unsigned old = atomicAdd(&g_ctr2, 1u);
        slast = (old == gridDim.x - 1) ? 1u : 0u;
        if (slast) { g_ctr1 = 0; g_ctr2 = 0; }               // replay-safe reset
    }
    __syncthreads();

    if (slast && warp == 0) {
        __threadfence();
        float v = 0.f;
        for (int i = lane; i < (int)gridDim.x; i += 32)      // fixed per-lane order
            v += __ldcg(&g_bsum[i]);
        #pragma unroll
        for (int o = 16; o; o >>= 1) v += __shfl_xor_sync(0xffffffffu, v, o);
        if (lane == 0) out[0] = v;
    }
}

// ---------------------------------------------------------------------------
extern "C" void kernel_launch(void* const* d_in, const int* in_sizes, int n_in,
                              void* d_out, int out_size) {
    const float* bre   = (const float*)d_in[0];
    const float* bim   = (const float*)d_in[1];
    const float* theta = (const float*)d_in[2];
    const float* evl   = (const float*)d_in[3];

    int sms = 148;
    cudaDeviceGetAttribute(&sms, cudaDevAttrMultiProcessorCount, 0);
    if (sms > 512) sms = 512;                                // g_bsum bound

    const int smem = 2 * NN * (int)sizeof(float);            // 128 KB
    cudaFuncSetAttribute(fused_kernel, cudaFuncAttributeMaxDynamicSharedMemorySize, smem);

    fused_kernel<<<sms, THREADS, smem>>>(bre, bim, theta, evl, (float*)d_out);
}